// round 13
// baseline (speedup 1.0000x reference)
#include <cuda_runtime.h>
#include <cuda_bf16.h>
#include <cuda_fp8.h>

#define BB   16
#define NN   128
#define HH   32
#define DD   5
#define NE1  1537     // NUM_EDGES + 1
#define NP1  129      // N + 1
#define RSTH 34       // bf16 row stride: phase-2 lane stride 17 banks (coprime 32)
#define TSCALE 256.0f // table stored as fp8 of (value * 256)

// Fused table in fp8 e4m3: T8[d][e][k] = e4m3( 256 * sum_h E[e,h]*Wdis[d,h,k] )
// Row = 32 bytes. Row e=0 is exactly zero.
__device__ __align__(16) __nv_fp8_e4m3 g_T8[DD * NE1 * HH];

// ---------------------------------------------------------------------------
// Prologue: 32 edges per block. grid=(ceil(1537/32), 5), block=(32,8)
// ---------------------------------------------------------------------------
__global__ void build_table_kernel(const float* __restrict__ E,     // (1537, 32)
                                   const float* __restrict__ Wdis)  // (>=5*32*32,)
{
    const int d  = blockIdx.y;
    const int k  = threadIdx.x;
    const int ey = threadIdx.y;

    __shared__ float Ws[HH * HH];
    __shared__ float Es[32][HH];

    const int t = ey * 32 + k;
    for (int i = t; i < HH * HH; i += 256) {
        Ws[i] = Wdis[d * HH * HH + i];
        const int e = blockIdx.x * 32 + i / HH;
        Es[i / HH][i % HH] = (e < NE1) ? E[e * HH + (i % HH)] : 0.f;
    }
    __syncthreads();

#pragma unroll
    for (int r = 0; r < 4; ++r) {
        const int el = ey + r * 8;
        const int e  = blockIdx.x * 32 + el;
        float acc = 0.f;
#pragma unroll
        for (int h = 0; h < HH; ++h)
            acc += Es[el][h] * Ws[h * HH + k];
        if (e < NE1)
            g_T8[(d * NE1 + e) * HH + k] = __nv_fp8_e4m3(acc * TSCALE);
    }
}

// decode 4x e4m3 (one uint32) into two f16x2 and accumulate
#define FP8_ACC(w, aLo, aHi) do {                                          \
    unsigned _lo, _hi;                                                     \
    asm("{\n\t.reg .b16 l, h;\n\t"                                         \
        "mov.b32 {l, h}, %2;\n\t"                                          \
        "cvt.rn.f16x2.e4m3x2 %0, l;\n\t"                                   \
        "cvt.rn.f16x2.e4m3x2 %1, h;\n\t}"                                  \
        : "=r"(_lo), "=r"(_hi) : "r"(w));                                  \
    asm("add.rn.f16x2 %0, %0, %1;" : "+r"(aLo) : "r"(_lo));                \
    asm("add.rn.f16x2 %0, %0, %1;" : "+r"(aHi) : "r"(_hi)); } while (0)

// ---------------------------------------------------------------------------
// Main: one block per (output row io, batch b). grid=(129, 16), block=256.
// ---------------------------------------------------------------------------
__global__ __launch_bounds__(256, 4)
void bias_kernel(const float* __restrict__ ab,        // (B, 129, 129)
                 const int*   __restrict__ spat,      // (B, 128, 128)
                 const int*   __restrict__ edge,      // (B, 128, 128, 5, 3)
                 const float* __restrict__ struct_w,  // (512, 32)
                 const float* __restrict__ virt,      // (1, 32)
                 float*       __restrict__ out)       // (B, 32, 129, 129)
{
    const int b    = blockIdx.y;
    const int io   = blockIdx.x;
    const int tid  = threadIdx.x;
    const int warp = tid >> 5;
    const int lane = tid & 31;

    // 16 ushorts per pair: 15 indices + spv. 32B/pair -> int4-aligned.
    __shared__ __align__(16) unsigned short sidxu[NN * 16];
    __shared__ __align__(8)  unsigned short rowh[NN * RSTH];  // bf16 bits
    __shared__ float ab_s[NP1];
    __shared__ float vs[HH];

    if (tid < HH)  vs[tid]   = virt[tid];
    if (tid < NP1) ab_s[tid] = ab[(b * NP1 + io) * NP1 + tid];

    if (io == 0) {
        __syncthreads();
#pragma unroll
        for (int hh = 0; hh < 4; ++hh) {
            const int h = warp + hh * 8;
            const float vh = vs[h];
            float* ob = out + (((size_t)b * HH + h) * NP1) * NP1;
#pragma unroll
            for (int k = 0; k < 5; ++k) {
                const int j = lane + 32 * k;
                if (j < NP1) ob[j] = fmaf(2.f, ab_s[j], vh);
            }
        }
        return;
    }

    const int ip    = io - 1;
    const int pbase = (b * NN + ip) * NN;

    // ---- stage indices (coalesced reads) as ushorts; slot 15 = spv ----
    {
        const int* gsrc = edge + (size_t)pbase * 15;
#pragma unroll
        for (int it = 0; it < 8; ++it) {
            const int i = tid + it * 256;
            if (i < NN * 15)
                sidxu[(i / 15) * 16 + (i % 15)] = (unsigned short)gsrc[i];
        }
        if (tid < NN) sidxu[tid * 16 + 15] = (unsigned short)spat[pbase + tid];
    }
    __syncthreads();

    // ---- phase 1: 8 lanes per pair, 4 pairs per warp-iteration ----
    const int g  = lane >> 3;          // pair group within warp (0..3)
    const int co = (lane & 7) * 4;     // this lane's 4 channels (bytes in fp8 row)
    const unsigned char* Tb = (const unsigned char*)g_T8 + co;

    const int jbase = warp * 4 + g;

#pragma unroll 1
    for (int k = 0; k < 4; ++k) {
        const int jl = k * 32 + jbase;                    // pair 0..127
        const uint4 qa = *(const uint4*)&sidxu[jl * 16];      // shorts 0..7
        const uint4 qb = *(const uint4*)&sidxu[jl * 16 + 8];  // shorts 8..15

        const int i0  = qa.x & 0xffff, i1  = qa.x >> 16;
        const int i2  = qa.y & 0xffff, i3  = qa.y >> 16;
        const int i4  = qa.z & 0xffff, i5  = qa.z >> 16;
        const int i6  = qa.w & 0xffff, i7  = qa.w >> 16;
        const int i8  = qb.x & 0xffff, i9  = qb.x >> 16;
        const int i10 = qb.y & 0xffff, i11 = qb.y >> 16;
        const int i12 = qb.z & 0xffff, i13 = qb.z >> 16;
        const int i14 = qb.w & 0xffff;
        const int spv = qb.w >> 16;

        // 15 independent LDG.32 fp8 gathers (d = t/3); row stride 32B
        const unsigned w0  = *(const unsigned*)(Tb + ((0 * NE1 + i0)  << 5));
        const unsigned w1  = *(const unsigned*)(Tb + ((0 * NE1 + i1)  << 5));
        const unsigned w2  = *(const unsigned*)(Tb + ((0 * NE1 + i2)  << 5));
        const unsigned w3  = *(const unsigned*)(Tb + ((1 * NE1 + i3)  << 5));
        const unsigned w4  = *(const unsigned*)(Tb + ((1 * NE1 + i4)  << 5));
        const unsigned w5  = *(const unsigned*)(Tb + ((1 * NE1 + i5)  << 5));
        const unsigned w6  = *(const unsigned*)(Tb + ((2 * NE1 + i6)  << 5));
        const unsigned w7  = *(const unsigned*)(Tb + ((2 * NE1 + i7)  << 5));
        const unsigned w8  = *(const unsigned*)(Tb + ((2 * NE1 + i8)  << 5));
        const unsigned w9  = *(const unsigned*)(Tb + ((3 * NE1 + i9)  << 5));
        const unsigned w10 = *(const unsigned*)(Tb + ((3 * NE1 + i10) << 5));
        const unsigned w11 = *(const unsigned*)(Tb + ((3 * NE1 + i11) << 5));
        const unsigned w12 = *(const unsigned*)(Tb + ((4 * NE1 + i12) << 5));
        const unsigned w13 = *(const unsigned*)(Tb + ((4 * NE1 + i13) << 5));
        const unsigned w14 = *(const unsigned*)(Tb + ((4 * NE1 + i14) << 5));
        const float4 sw = *(const float4*)(struct_w + spv * HH + co);

        // scale off the critical path (MUFU 16cyc); includes /TSCALE
        const int sp = (spv <= 1) ? 1 : min(spv - 1, DD);
        float sc;
        asm("rcp.approx.f32 %0, %1;" : "=f"(sc) : "f"(3.0f * TSCALE * (float)sp));

        // decode + accumulate in two f16x2 accumulator sets (A/B interleave)
        unsigned aLo = 0, aHi = 0, bLo = 0, bHi = 0;
        FP8_ACC(w0,  aLo, aHi);  FP8_ACC(w1,  bLo, bHi);
        FP8_ACC(w2,  aLo, aHi);  FP8_ACC(w3,  bLo, bHi);
        FP8_ACC(w4,  aLo, aHi);  FP8_ACC(w5,  bLo, bHi);
        FP8_ACC(w6,  aLo, aHi);  FP8_ACC(w7,  bLo, bHi);
        FP8_ACC(w8,  aLo, aHi);  FP8_ACC(w9,  bLo, bHi);
        FP8_ACC(w10, aLo, aHi);  FP8_ACC(w11, bLo, bHi);
        FP8_ACC(w12, aLo, aHi);  FP8_ACC(w13, bLo, bHi);
        FP8_ACC(w14, aLo, aHi);
        asm("add.rn.f16x2 %0, %0, %1;" : "+r"(aLo) : "r"(bLo));
        asm("add.rn.f16x2 %0, %0, %1;" : "+r"(aHi) : "r"(bHi));

        // widen f16x2 -> 4x f32
        float f0, f1, f2, f3;
        asm("{\n\t.reg .b16 l, h;\n\tmov.b32 {l, h}, %2;\n\t"
            "cvt.f32.f16 %0, l;\n\tcvt.f32.f16 %1, h;\n\t}"
            : "=f"(f0), "=f"(f1) : "r"(aLo));
        asm("{\n\t.reg .b16 l, h;\n\tmov.b32 {l, h}, %2;\n\t"
            "cvt.f32.f16 %0, l;\n\tcvt.f32.f16 %1, h;\n\t}"
            : "=f"(f2), "=f"(f3) : "r"(aHi));

        const float r0 = fmaf(f0, sc, sw.x);
        const float r1 = fmaf(f1, sc, sw.y);
        const float r2 = fmaf(f2, sc, sw.z);
        const float r3 = fmaf(f3, sc, sw.w);

        // pack to bf16x2 pairs and store (2x STS.32, <=2-way conflicts)
        unsigned p01, p23;
        asm("cvt.rn.bf16x2.f32 %0, %1, %2;" : "=r"(p01) : "f"(r1), "f"(r0));
        asm("cvt.rn.bf16x2.f32 %0, %1, %2;" : "=r"(p23) : "f"(r3), "f"(r2));
        *(unsigned*)&rowh[jl * RSTH + co]     = p01;
        *(unsigned*)&rowh[jl * RSTH + co + 2] = p23;
    }
    __syncthreads();

    // ---- phase 2: emit 32 x 129 slab; bf16 row reads, conflict-free ----
    const int j1 = 1 + lane;
    const float a0 = ab_s[j1];
    const float a1 = ab_s[j1 + 32];
    const float a2 = ab_s[j1 + 64];
    const float a3 = ab_s[j1 + 96];
    const float az = ab_s[0];

#pragma unroll
    for (int hh = 0; hh < 4; ++hh) {
        const int h  = warp + hh * 8;
        const float vh = vs[h];
        float* ob = out + (((size_t)b * HH + h) * NP1 + io) * NP1;
        if (lane == 0) ob[0] = fmaf(2.f, az, vh);
        const float r0 = __uint_as_float((unsigned)rowh[(lane)      * RSTH + h] << 16);
        const float r1 = __uint_as_float((unsigned)rowh[(lane + 32) * RSTH + h] << 16);
        const float r2 = __uint_as_float((unsigned)rowh[(lane + 64) * RSTH + h] << 16);
        const float r3 = __uint_as_float((unsigned)rowh[(lane + 96) * RSTH + h] << 16);
        ob[j1]      = fmaf(2.f, a0, r0);
        ob[j1 + 32] = fmaf(2.f, a1, r1);
        ob[j1 + 64] = fmaf(2.f, a2, r2);
        ob[j1 + 96] = fmaf(2.f, a3, r3);
    }
}

// ---------------------------------------------------------------------------
extern "C" void kernel_launch(void* const* d_in, const int* in_sizes, int n_in,
                              void* d_out, int out_size)
{
    const float* ab    = (const float*)d_in[1];
    const int*   spat  = (const int*)  d_in[2];
    const int*   edge  = (const int*)  d_in[3];
    const float* ew    = (const float*)d_in[4];
    const float* sw    = (const float*)d_in[5];
    const float* wdis  = (const float*)d_in[6];
    const float* virt  = (const float*)d_in[7];
    float*       outp  = (float*)d_out;

    build_table_kernel<<<dim3((NE1 + 31) / 32, DD), dim3(32, 8)>>>(ew, wdis);
    bias_kernel<<<dim3(NP1, BB), 256>>>(ab, spat, edge, sw, virt, outp);
}

// round 14
// speedup vs baseline: 1.0754x; 1.0754x over previous
#include <cuda_runtime.h>
#include <cuda_bf16.h>
#include <cuda_fp8.h>

#define BB   16
#define NN   128
#define HH   32
#define DD   5
#define NE1  1537     // NUM_EDGES + 1
#define NP1  129      // N + 1
#define RSTH 34       // bf16 row stride: phase-2 lane stride 17 banks (coprime 32)
#define TSCALE 256.0f // table stored as fp8 of (value * 256)

// Fused table in fp8 e4m3: T8[d][e][k] = e4m3( 256 * sum_h E[e,h]*Wdis[d,h,k] )
// Row = 32 bytes. Row e=0 is exactly zero.
__device__ __align__(16) __nv_fp8_e4m3 g_T8[DD * NE1 * HH];

// ---------------------------------------------------------------------------
// Prologue (R12 form): 8 edges per block. grid=(ceil(1537/8), 5), block=(32,8)
// ---------------------------------------------------------------------------
__global__ void build_table_kernel(const float* __restrict__ E,     // (1537, 32)
                                   const float* __restrict__ Wdis)  // (>=5*32*32,)
{
    const int d  = blockIdx.y;
    const int k  = threadIdx.x;
    const int ey = threadIdx.y;
    const int e  = blockIdx.x * 8 + ey;

    __shared__ float Ws[HH * HH];
    __shared__ float Es[8][HH];

    const int t = ey * 32 + k;
    for (int i = t; i < HH * HH; i += 256)
        Ws[i] = Wdis[d * HH * HH + i];
    Es[ey][k] = (e < NE1) ? E[e * HH + k] : 0.f;
    __syncthreads();

    if (e < NE1) {
        float acc = 0.f;
#pragma unroll
        for (int h = 0; h < HH; ++h)
            acc += Es[ey][h] * Ws[h * HH + k];
        g_T8[(d * NE1 + e) * HH + k] = __nv_fp8_e4m3(acc * TSCALE);
    }
}

// decode 4x e4m3 (one uint32) into two f16x2 and accumulate
#define FP8_ACC(w, aLo, aHi) do {                                          \
    unsigned _lo, _hi;                                                     \
    asm("{\n\t.reg .b16 l, h;\n\t"                                         \
        "mov.b32 {l, h}, %2;\n\t"                                          \
        "cvt.rn.f16x2.e4m3x2 %0, l;\n\t"                                   \
        "cvt.rn.f16x2.e4m3x2 %1, h;\n\t}"                                  \
        : "=r"(_lo), "=r"(_hi) : "r"(w));                                  \
    asm("add.rn.f16x2 %0, %0, %1;" : "+r"(aLo) : "r"(_lo));                \
    asm("add.rn.f16x2 %0, %0, %1;" : "+r"(aHi) : "r"(_hi)); } while (0)

// ---------------------------------------------------------------------------
// Main: one block per (output row io, batch b). grid=(129, 16), block=256.
// ---------------------------------------------------------------------------
__global__ __launch_bounds__(256, 4)
void bias_kernel(const float* __restrict__ ab,        // (B, 129, 129)
                 const int*   __restrict__ spat,      // (B, 128, 128)
                 const int*   __restrict__ edge,      // (B, 128, 128, 5, 3)
                 const float* __restrict__ struct_w,  // (512, 32)
                 const float* __restrict__ virt,      // (1, 32)
                 float*       __restrict__ out)       // (B, 32, 129, 129)
{
    const int b    = blockIdx.y;
    const int io   = blockIdx.x;
    const int tid  = threadIdx.x;
    const int warp = tid >> 5;
    const int lane = tid & 31;

    // 16 ushorts per pair: 15 PRE-SHIFTED indices (e<<5 = byte row offset,
    // max 49152 fits ushort) + spv. 32B/pair -> int4-aligned.
    __shared__ __align__(16) unsigned short sidxu[NN * 16];
    __shared__ __align__(8)  unsigned short rowh[NN * RSTH];  // bf16 bits
    __shared__ float ab_s[NP1];
    __shared__ float vs[HH];

    if (tid < HH)  vs[tid]   = virt[tid];
    if (tid < NP1) ab_s[tid] = ab[(b * NP1 + io) * NP1 + tid];

    if (io == 0) {
        __syncthreads();
#pragma unroll
        for (int hh = 0; hh < 4; ++hh) {
            const int h = warp + hh * 8;
            const float vh = vs[h];
            float* ob = out + (((size_t)b * HH + h) * NP1) * NP1;
#pragma unroll
            for (int k = 0; k < 5; ++k) {
                const int j = lane + 32 * k;
                if (j < NP1) ob[j] = fmaf(2.f, ab_s[j], vh);
            }
        }
        return;
    }

    const int ip    = io - 1;
    const int pbase = (b * NN + ip) * NN;

    // ---- stage pre-shifted indices (coalesced reads); slot 15 = spv ----
    {
        const int* gsrc = edge + (size_t)pbase * 15;
#pragma unroll
        for (int it = 0; it < 8; ++it) {
            const int i = tid + it * 256;
            if (i < NN * 15)
                sidxu[(i / 15) * 16 + (i % 15)] = (unsigned short)(gsrc[i] << 5);
        }
        if (tid < NN) sidxu[tid * 16 + 15] = (unsigned short)spat[pbase + tid];
    }
    __syncthreads();

    // ---- phase 1: 8 lanes per pair, 4 pairs per warp-iteration ----
    const int g  = lane >> 3;          // pair group within warp (0..3)
    const int co = (lane & 7) * 4;     // this lane's 4 channels (bytes in fp8 row)
    const unsigned char* Tb0 = (const unsigned char*)g_T8 + co;
    const unsigned char* Tb1 = Tb0 + 1 * NE1 * HH;
    const unsigned char* Tb2 = Tb0 + 2 * NE1 * HH;
    const unsigned char* Tb3 = Tb0 + 3 * NE1 * HH;
    const unsigned char* Tb4 = Tb0 + 4 * NE1 * HH;

    const int jbase = warp * 4 + g;

#pragma unroll 1
    for (int k = 0; k < 4; ++k) {
        const int jl = k * 32 + jbase;                    // pair 0..127
        const uint4 qa = *(const uint4*)&sidxu[jl * 16];      // shorts 0..7
        const uint4 qb = *(const uint4*)&sidxu[jl * 16 + 8];  // shorts 8..15

        // pre-shifted byte offsets: just mask/shift, no multiply
        const unsigned o0  = qa.x & 0xffffu, o1  = qa.x >> 16;
        const unsigned o2  = qa.y & 0xffffu, o3  = qa.y >> 16;
        const unsigned o4  = qa.z & 0xffffu, o5  = qa.z >> 16;
        const unsigned o6  = qa.w & 0xffffu, o7  = qa.w >> 16;
        const unsigned o8  = qb.x & 0xffffu, o9  = qb.x >> 16;
        const unsigned o10 = qb.y & 0xffffu, o11 = qb.y >> 16;
        const unsigned o12 = qb.z & 0xffffu, o13 = qb.z >> 16;
        const unsigned o14 = qb.w & 0xffffu;
        const int spv = (int)(qb.w >> 16);

        // 15 independent LDG.32 fp8 gathers (d = t/3); offsets pre-scaled
        const unsigned w0  = *(const unsigned*)(Tb0 + o0);
        const unsigned w1  = *(const unsigned*)(Tb0 + o1);
        const unsigned w2  = *(const unsigned*)(Tb0 + o2);
        const unsigned w3  = *(const unsigned*)(Tb1 + o3);
        const unsigned w4  = *(const unsigned*)(Tb1 + o4);
        const unsigned w5  = *(const unsigned*)(Tb1 + o5);
        const unsigned w6  = *(const unsigned*)(Tb2 + o6);
        const unsigned w7  = *(const unsigned*)(Tb2 + o7);
        const unsigned w8  = *(const unsigned*)(Tb2 + o8);
        const unsigned w9  = *(const unsigned*)(Tb3 + o9);
        const unsigned w10 = *(const unsigned*)(Tb3 + o10);
        const unsigned w11 = *(const unsigned*)(Tb3 + o11);
        const unsigned w12 = *(const unsigned*)(Tb4 + o12);
        const unsigned w13 = *(const unsigned*)(Tb4 + o13);
        const unsigned w14 = *(const unsigned*)(Tb4 + o14);
        const float4 sw = *(const float4*)(struct_w + spv * HH + co);

        // scale off the critical path (MUFU 16cyc); includes /TSCALE
        const int sp = (spv <= 1) ? 1 : min(spv - 1, DD);
        float sc;
        asm("rcp.approx.f32 %0, %1;" : "=f"(sc) : "f"(3.0f * TSCALE * (float)sp));

        // decode + accumulate in two f16x2 accumulator sets (A/B interleave)
        unsigned aLo = 0, aHi = 0, bLo = 0, bHi = 0;
        FP8_ACC(w0,  aLo, aHi);  FP8_ACC(w1,  bLo, bHi);
        FP8_ACC(w2,  aLo, aHi);  FP8_ACC(w3,  bLo, bHi);
        FP8_ACC(w4,  aLo, aHi);  FP8_ACC(w5,  bLo, bHi);
        FP8_ACC(w6,  aLo, aHi);  FP8_ACC(w7,  bLo, bHi);
        FP8_ACC(w8,  aLo, aHi);  FP8_ACC(w9,  bLo, bHi);
        FP8_ACC(w10, aLo, aHi);  FP8_ACC(w11, bLo, bHi);
        FP8_ACC(w12, aLo, aHi);  FP8_ACC(w13, bLo, bHi);
        FP8_ACC(w14, aLo, aHi);
        asm("add.rn.f16x2 %0, %0, %1;" : "+r"(aLo) : "r"(bLo));
        asm("add.rn.f16x2 %0, %0, %1;" : "+r"(aHi) : "r"(bHi));

        // widen f16x2 -> 4x f32
        float f0, f1, f2, f3;
        asm("{\n\t.reg .b16 l, h;\n\tmov.b32 {l, h}, %2;\n\t"
            "cvt.f32.f16 %0, l;\n\tcvt.f32.f16 %1, h;\n\t}"
            : "=f"(f0), "=f"(f1) : "r"(aLo));
        asm("{\n\t.reg .b16 l, h;\n\tmov.b32 {l, h}, %2;\n\t"
            "cvt.f32.f16 %0, l;\n\tcvt.f32.f16 %1, h;\n\t}"
            : "=f"(f2), "=f"(f3) : "r"(aHi));

        const float r0 = fmaf(f0, sc, sw.x);
        const float r1 = fmaf(f1, sc, sw.y);
        const float r2 = fmaf(f2, sc, sw.z);
        const float r3 = fmaf(f3, sc, sw.w);

        // pack to bf16x2 pairs and store (2x STS.32, <=2-way conflicts)
        unsigned p01, p23;
        asm("cvt.rn.bf16x2.f32 %0, %1, %2;" : "=r"(p01) : "f"(r1), "f"(r0));
        asm("cvt.rn.bf16x2.f32 %0, %1, %2;" : "=r"(p23) : "f"(r3), "f"(r2));
        *(unsigned*)&rowh[jl * RSTH + co]     = p01;
        *(unsigned*)&rowh[jl * RSTH + co + 2] = p23;
    }
    __syncthreads();

    // ---- phase 2: emit 32 x 129 slab; bf16 row reads, conflict-free ----
    const int j1 = 1 + lane;
    const float a0 = ab_s[j1];
    const float a1 = ab_s[j1 + 32];
    const float a2 = ab_s[j1 + 64];
    const float a3 = ab_s[j1 + 96];
    const float az = ab_s[0];

#pragma unroll
    for (int hh = 0; hh < 4; ++hh) {
        const int h  = warp + hh * 8;
        const float vh = vs[h];
        float* ob = out + (((size_t)b * HH + h) * NP1 + io) * NP1;
        if (lane == 0) ob[0] = fmaf(2.f, az, vh);
        const float r0 = __uint_as_float((unsigned)rowh[(lane)      * RSTH + h] << 16);
        const float r1 = __uint_as_float((unsigned)rowh[(lane + 32) * RSTH + h] << 16);
        const float r2 = __uint_as_float((unsigned)rowh[(lane + 64) * RSTH + h] << 16);
        const float r3 = __uint_as_float((unsigned)rowh[(lane + 96) * RSTH + h] << 16);
        ob[j1]      = fmaf(2.f, a0, r0);
        ob[j1 + 32] = fmaf(2.f, a1, r1);
        ob[j1 + 64] = fmaf(2.f, a2, r2);
        ob[j1 + 96] = fmaf(2.f, a3, r3);
    }
}

// ---------------------------------------------------------------------------
extern "C" void kernel_launch(void* const* d_in, const int* in_sizes, int n_in,
                              void* d_out, int out_size)
{
    const float* ab    = (const float*)d_in[1];
    const int*   spat  = (const int*)  d_in[2];
    const int*   edge  = (const int*)  d_in[3];
    const float* ew    = (const float*)d_in[4];
    const float* sw    = (const float*)d_in[5];
    const float* wdis  = (const float*)d_in[6];
    const float* virt  = (const float*)d_in[7];
    float*       outp  = (float*)d_out;

    build_table_kernel<<<dim3((NE1 + 7) / 8, DD), dim3(32, 8)>>>(ew, wdis);
    bias_kernel<<<dim3(NP1, BB), 256>>>(ab, spat, edge, sw, virt, outp);
}

// round 15
// speedup vs baseline: 1.0789x; 1.0033x over previous
#include <cuda_runtime.h>
#include <cuda_bf16.h>
#include <cuda_fp8.h>

#define BB   16
#define NN   128
#define HH   32
#define DD   5
#define NE1  1537     // NUM_EDGES + 1
#define NP1  129      // N + 1
#define RSTH 34       // bf16 row stride: phase-2 lane stride 17 banks (coprime 32)
#define TSCALE 256.0f // table stored as fp8 of (value * 256)

// Fused table in fp8 e4m3: T8[d][e][k] = e4m3( 256 * sum_h E[e,h]*Wdis[d,h,k] )
// Row = 32 bytes. Row e=0 is exactly zero.
__device__ __align__(16) __nv_fp8_e4m3 g_T8[DD * NE1 * HH];

// ---------------------------------------------------------------------------
// Prologue: 8 edges per block. grid=(ceil(1537/8), 5), block=(32,8)
// Signals dependent launch as soon as its stores are issued.
// ---------------------------------------------------------------------------
__global__ void build_table_kernel(const float* __restrict__ E,     // (1537, 32)
                                   const float* __restrict__ Wdis)  // (>=5*32*32,)
{
    const int d  = blockIdx.y;
    const int k  = threadIdx.x;
    const int ey = threadIdx.y;
    const int e  = blockIdx.x * 8 + ey;

    __shared__ float Ws[HH * HH];
    __shared__ float Es[8][HH];

    const int t = ey * 32 + k;
    for (int i = t; i < HH * HH; i += 256)
        Ws[i] = Wdis[d * HH * HH + i];
    Es[ey][k] = (e < NE1) ? E[e * HH + k] : 0.f;
    __syncthreads();

    if (e < NE1) {
        float acc = 0.f;
#pragma unroll
        for (int h = 0; h < HH; ++h)
            acc += Es[ey][h] * Ws[h * HH + k];
        g_T8[(d * NE1 + e) * HH + k] = __nv_fp8_e4m3(acc * TSCALE);
    }

    // PDL: allow dependent grid to start launching now.
    asm volatile("griddepcontrol.launch_dependents;");
}

// decode 4x e4m3 (one uint32) into two f16x2 and accumulate
#define FP8_ACC(w, aLo, aHi) do {                                          \
    unsigned _lo, _hi;                                                     \
    asm("{\n\t.reg .b16 l, h;\n\t"                                         \
        "mov.b32 {l, h}, %2;\n\t"                                          \
        "cvt.rn.f16x2.e4m3x2 %0, l;\n\t"                                   \
        "cvt.rn.f16x2.e4m3x2 %1, h;\n\t}"                                  \
        : "=r"(_lo), "=r"(_hi) : "r"(w));                                  \
    asm("add.rn.f16x2 %0, %0, %1;" : "+r"(aLo) : "r"(_lo));                \
    asm("add.rn.f16x2 %0, %0, %1;" : "+r"(aHi) : "r"(_hi)); } while (0)

// ---------------------------------------------------------------------------
// Main: one block per (output row io, batch b). grid=(129, 16), block=256.
// Launched with programmatic stream serialization; waits for build_table's
// memory only on the path that reads the table (after its own prologue).
// ---------------------------------------------------------------------------
__global__ __launch_bounds__(256, 4)
void bias_kernel(const float* __restrict__ ab,        // (B, 129, 129)
                 const int*   __restrict__ spat,      // (B, 128, 128)
                 const int*   __restrict__ edge,      // (B, 128, 128, 5, 3)
                 const float* __restrict__ struct_w,  // (512, 32)
                 const float* __restrict__ virt,      // (1, 32)
                 float*       __restrict__ out)       // (B, 32, 129, 129)
{
    const int b    = blockIdx.y;
    const int io   = blockIdx.x;
    const int tid  = threadIdx.x;
    const int warp = tid >> 5;
    const int lane = tid & 31;

    // 16 ushorts per pair: 15 PRE-SHIFTED indices (e<<5 = byte row offset,
    // max 49152 fits ushort) + spv. 32B/pair -> int4-aligned.
    __shared__ __align__(16) unsigned short sidxu[NN * 16];
    __shared__ __align__(8)  unsigned short rowh[NN * RSTH];  // bf16 bits
    __shared__ float ab_s[NP1];
    __shared__ float vs[HH];

    if (tid < HH)  vs[tid]   = virt[tid];
    if (tid < NP1) ab_s[tid] = ab[(b * NP1 + io) * NP1 + tid];

    if (io == 0) {
        // no table dependency on this path
        __syncthreads();
#pragma unroll
        for (int hh = 0; hh < 4; ++hh) {
            const int h = warp + hh * 8;
            const float vh = vs[h];
            float* ob = out + (((size_t)b * HH + h) * NP1) * NP1;
#pragma unroll
            for (int k = 0; k < 5; ++k) {
                const int j = lane + 32 * k;
                if (j < NP1) ob[j] = fmaf(2.f, ab_s[j], vh);
            }
        }
        return;
    }

    const int ip    = io - 1;
    const int pbase = (b * NN + ip) * NN;

    // ---- stage pre-shifted indices (coalesced reads); slot 15 = spv ----
    {
        const int* gsrc = edge + (size_t)pbase * 15;
#pragma unroll
        for (int it = 0; it < 8; ++it) {
            const int i = tid + it * 256;
            if (i < NN * 15)
                sidxu[(i / 15) * 16 + (i % 15)] = (unsigned short)(gsrc[i] << 5);
        }
        if (tid < NN) sidxu[tid * 16 + 15] = (unsigned short)spat[pbase + tid];
    }
    __syncthreads();

    // PDL: table reads start below — wait for build_table's stores now.
    asm volatile("griddepcontrol.wait;");

    // ---- phase 1: 8 lanes per pair, 4 pairs per warp-iteration ----
    const int g  = lane >> 3;          // pair group within warp (0..3)
    const int co = (lane & 7) * 4;     // this lane's 4 channels (bytes in fp8 row)
    const unsigned char* Tb0 = (const unsigned char*)g_T8 + co;
    const unsigned char* Tb1 = Tb0 + 1 * NE1 * HH;
    const unsigned char* Tb2 = Tb0 + 2 * NE1 * HH;
    const unsigned char* Tb3 = Tb0 + 3 * NE1 * HH;
    const unsigned char* Tb4 = Tb0 + 4 * NE1 * HH;

    const int jbase = warp * 4 + g;

#pragma unroll 1
    for (int k = 0; k < 4; ++k) {
        const int jl = k * 32 + jbase;                    // pair 0..127
        const uint4 qa = *(const uint4*)&sidxu[jl * 16];      // shorts 0..7
        const uint4 qb = *(const uint4*)&sidxu[jl * 16 + 8];  // shorts 8..15

        // pre-shifted byte offsets: just mask/shift, no multiply
        const unsigned o0  = qa.x & 0xffffu, o1  = qa.x >> 16;
        const unsigned o2  = qa.y & 0xffffu, o3  = qa.y >> 16;
        const unsigned o4  = qa.z & 0xffffu, o5  = qa.z >> 16;
        const unsigned o6  = qa.w & 0xffffu, o7  = qa.w >> 16;
        const unsigned o8  = qb.x & 0xffffu, o9  = qb.x >> 16;
        const unsigned o10 = qb.y & 0xffffu, o11 = qb.y >> 16;
        const unsigned o12 = qb.z & 0xffffu, o13 = qb.z >> 16;
        const unsigned o14 = qb.w & 0xffffu;
        const int spv = (int)(qb.w >> 16);

        // 15 independent LDG.32 fp8 gathers (d = t/3); offsets pre-scaled
        const unsigned w0  = *(const unsigned*)(Tb0 + o0);
        const unsigned w1  = *(const unsigned*)(Tb0 + o1);
        const unsigned w2  = *(const unsigned*)(Tb0 + o2);
        const unsigned w3  = *(const unsigned*)(Tb1 + o3);
        const unsigned w4  = *(const unsigned*)(Tb1 + o4);
        const unsigned w5  = *(const unsigned*)(Tb1 + o5);
        const unsigned w6  = *(const unsigned*)(Tb2 + o6);
        const unsigned w7  = *(const unsigned*)(Tb2 + o7);
        const unsigned w8  = *(const unsigned*)(Tb2 + o8);
        const unsigned w9  = *(const unsigned*)(Tb3 + o9);
        const unsigned w10 = *(const unsigned*)(Tb3 + o10);
        const unsigned w11 = *(const unsigned*)(Tb3 + o11);
        const unsigned w12 = *(const unsigned*)(Tb4 + o12);
        const unsigned w13 = *(const unsigned*)(Tb4 + o13);
        const unsigned w14 = *(const unsigned*)(Tb4 + o14);
        const float4 sw = *(const float4*)(struct_w + spv * HH + co);

        // scale off the critical path (MUFU 16cyc); includes /TSCALE
        const int sp = (spv <= 1) ? 1 : min(spv - 1, DD);
        float sc;
        asm("rcp.approx.f32 %0, %1;" : "=f"(sc) : "f"(3.0f * TSCALE * (float)sp));

        // decode + accumulate in two f16x2 accumulator sets (A/B interleave)
        unsigned aLo = 0, aHi = 0, bLo = 0, bHi = 0;
        FP8_ACC(w0,  aLo, aHi);  FP8_ACC(w1,  bLo, bHi);
        FP8_ACC(w2,  aLo, aHi);  FP8_ACC(w3,  bLo, bHi);
        FP8_ACC(w4,  aLo, aHi);  FP8_ACC(w5,  bLo, bHi);
        FP8_ACC(w6,  aLo, aHi);  FP8_ACC(w7,  bLo, bHi);
        FP8_ACC(w8,  aLo, aHi);  FP8_ACC(w9,  bLo, bHi);
        FP8_ACC(w10, aLo, aHi);  FP8_ACC(w11, bLo, bHi);
        FP8_ACC(w12, aLo, aHi);  FP8_ACC(w13, bLo, bHi);
        FP8_ACC(w14, aLo, aHi);
        asm("add.rn.f16x2 %0, %0, %1;" : "+r"(aLo) : "r"(bLo));
        asm("add.rn.f16x2 %0, %0, %1;" : "+r"(aHi) : "r"(bHi));

        // widen f16x2 -> 4x f32
        float f0, f1, f2, f3;
        asm("{\n\t.reg .b16 l, h;\n\tmov.b32 {l, h}, %2;\n\t"
            "cvt.f32.f16 %0, l;\n\tcvt.f32.f16 %1, h;\n\t}"
            : "=f"(f0), "=f"(f1) : "r"(aLo));
        asm("{\n\t.reg .b16 l, h;\n\tmov.b32 {l, h}, %2;\n\t"
            "cvt.f32.f16 %0, l;\n\tcvt.f32.f16 %1, h;\n\t}"
            : "=f"(f2), "=f"(f3) : "r"(aHi));

        const float r0 = fmaf(f0, sc, sw.x);
        const float r1 = fmaf(f1, sc, sw.y);
        const float r2 = fmaf(f2, sc, sw.z);
        const float r3 = fmaf(f3, sc, sw.w);

        // pack to bf16x2 pairs and store (2x STS.32, <=2-way conflicts)
        unsigned p01, p23;
        asm("cvt.rn.bf16x2.f32 %0, %1, %2;" : "=r"(p01) : "f"(r1), "f"(r0));
        asm("cvt.rn.bf16x2.f32 %0, %1, %2;" : "=r"(p23) : "f"(r3), "f"(r2));
        *(unsigned*)&rowh[jl * RSTH + co]     = p01;
        *(unsigned*)&rowh[jl * RSTH + co + 2] = p23;
    }
    __syncthreads();

    // ---- phase 2: emit 32 x 129 slab; bf16 row reads, conflict-free ----
    const int j1 = 1 + lane;
    const float a0 = ab_s[j1];
    const float a1 = ab_s[j1 + 32];
    const float a2 = ab_s[j1 + 64];
    const float a3 = ab_s[j1 + 96];
    const float az = ab_s[0];

#pragma unroll
    for (int hh = 0; hh < 4; ++hh) {
        const int h  = warp + hh * 8;
        const float vh = vs[h];
        float* ob = out + (((size_t)b * HH + h) * NP1 + io) * NP1;
        if (lane == 0) ob[0] = fmaf(2.f, az, vh);
        const float r0 = __uint_as_float((unsigned)rowh[(lane)      * RSTH + h] << 16);
        const float r1 = __uint_as_float((unsigned)rowh[(lane + 32) * RSTH + h] << 16);
        const float r2 = __uint_as_float((unsigned)rowh[(lane + 64) * RSTH + h] << 16);
        const float r3 = __uint_as_float((unsigned)rowh[(lane + 96) * RSTH + h] << 16);
        ob[j1]      = fmaf(2.f, a0, r0);
        ob[j1 + 32] = fmaf(2.f, a1, r1);
        ob[j1 + 64] = fmaf(2.f, a2, r2);
        ob[j1 + 96] = fmaf(2.f, a3, r3);
    }
}

// ---------------------------------------------------------------------------
extern "C" void kernel_launch(void* const* d_in, const int* in_sizes, int n_in,
                              void* d_out, int out_size)
{
    const float* ab    = (const float*)d_in[1];
    const int*   spat  = (const int*)  d_in[2];
    const int*   edge  = (const int*)  d_in[3];
    const float* ew    = (const float*)d_in[4];
    const float* sw    = (const float*)d_in[5];
    const float* wdis  = (const float*)d_in[6];
    const float* virt  = (const float*)d_in[7];
    float*       outp  = (float*)d_out;

    build_table_kernel<<<dim3((NE1 + 7) / 8, DD), dim3(32, 8)>>>(ew, wdis);

    // bias_kernel with programmatic dependent launch (overlaps build_table)
    cudaLaunchConfig_t cfg = {};
    cfg.gridDim  = dim3(NP1, BB);
    cfg.blockDim = dim3(256);
    cudaLaunchAttribute attrs[1];
    attrs[0].id = cudaLaunchAttributeProgrammaticStreamSerialization;
    attrs[0].val.programmaticStreamSerializationAllowed = 1;
    cfg.attrs = attrs;
    cfg.numAttrs = 1;
    cudaLaunchKernelEx(&cfg, bias_kernel, ab, spat, edge, sw, virt, outp);
}